// round 1
// baseline (speedup 1.0000x reference)
#include <cuda_runtime.h>

// NablaT 3D: out[z,y,x] = bdiff_z(x0) + bdiff_y(x1) + bdiff_x(x2)
// bdiff along dim d: out[0] = -v[0]; out[i] = v[i-1] - v[i]; out[S-1] = v[S-2]
// i.e. out[i] = a - b with a = (i>0)? v[i-1] : 0, b = (i<S-1)? v[i] : 0.
//
// x: [3, 320, 320, 320] fp32 contiguous. out: [320,320,320] fp32.
// Vectorized: each thread produces 4 x-contiguous outputs (float4).

#define S 320
#define PLANE (S * S)           // 102400
#define VOL (S * S * S)         // 32768000
#define X4 (S / 4)              // 80 float4 per row

__global__ __launch_bounds__(320, 4)
void nablat_kernel(const float* __restrict__ xin, float* __restrict__ out) {
    const int x4 = threadIdx.x;                         // 0..79
    const int y  = blockIdx.y * blockDim.y + threadIdx.y; // 0..319
    const int z  = blockIdx.z;                          // 0..319
    const int xi = x4 * 4;

    const long base = (long)z * PLANE + (long)y * S + xi;
    const long b4   = base >> 2;

    const float4* __restrict__ p0 = (const float4*)(xin);
    const float4* __restrict__ p1 = (const float4*)(xin + (long)VOL);
    const float4* __restrict__ p2 = (const float4*)(xin + 2L * VOL);
    const float*  __restrict__ s2 = xin + 2L * VOL;

    const float4 zero = make_float4(0.f, 0.f, 0.f, 0.f);

    // axis 0 (z): a0 = x0[z-1], b0 = x0[z] (b zeroed at z==S-1)
    float4 b0 = (z < S - 1) ? __ldg(&p0[b4])             : zero;
    float4 a0 = (z > 0)     ? __ldg(&p0[b4 - PLANE / 4]) : zero;

    // axis 1 (y): a1 = x1[y-1], b1 = x1[y]
    float4 b1 = (y < S - 1) ? __ldg(&p1[b4])             : zero;
    float4 a1 = (y > 0)     ? __ldg(&p1[b4 - S / 4])     : zero;

    // axis 2 (x): within-vector shift; halo element at xi-1
    float4 v2   = __ldg(&p2[b4]);
    float  prev = (xi > 0) ? __ldg(&s2[base - 1]) : 0.f;
    // last lane of last vector in a row: b = 0 (x == S-1)
    float b2w = (x4 == X4 - 1) ? 0.f : v2.w;

    float4 o;
    o.x = (a0.x - b0.x) + (a1.x - b1.x) + (prev - v2.x);
    o.y = (a0.y - b0.y) + (a1.y - b1.y) + (v2.x - v2.y);
    o.z = (a0.z - b0.z) + (a1.z - b1.z) + (v2.y - v2.z);
    o.w = (a0.w - b0.w) + (a1.w - b1.w) + (v2.z - b2w);

    ((float4*)out)[b4] = o;
}

extern "C" void kernel_launch(void* const* d_in, const int* in_sizes, int n_in,
                              void* d_out, int out_size) {
    const float* x = (const float*)d_in[0];
    float* out = (float*)d_out;

    dim3 block(X4, 4, 1);        // 320 threads: one thread per float4, 4 rows
    dim3 grid(1, S / 4, S);      // (1, 80, 320)
    nablat_kernel<<<grid, block>>>(x, out);
}